// round 16
// baseline (speedup 1.0000x reference)
#include <cuda_runtime.h>
#include <cuda_bf16.h>
#include <cuda_fp16.h>
#include <math.h>
#include <stdint.h>

// Problem constants (fixed by the dataset)
#define NN 50000
#define EE 1600000
#define D_IN 256
#define D_H1 128
#define D_H2 64

// ---------------- scratch (static device globals; no allocation) ----------------
static __device__ __align__(16) uint32_t g_h1[(size_t)NN * D_H1];  // packed hi/lo
static __device__ __align__(16) uint32_t g_h2[(size_t)NN * D_H2];  // packed hi/lo
static __device__ __align__(16) __half   g_hw[(size_t)NN * D_H2];  // fp16 (spmm gathers)
static __device__ __align__(16) uint32_t g_g [(size_t)NN * D_H2];  // packed hi/lo
static __device__ float g_dinv[NN];
static __device__ float g_degf[NN];
static __device__ int   g_counts[NN];
static __device__ int   g_cursor[NN];
static __device__ int   g_rowptr[NN + 1];
static __device__ int   g_partials[64];
static __device__ __align__(8) int2 g_csr[EE];   // .x = src, .y = float bits of coeff

// pre-split weights (hi/lo bf16), concatenated
#define W_TOTAL 90112
static __device__ __align__(16) __nv_bfloat16 g_wh[W_TOTAL];
static __device__ __align__(16) __nv_bfloat16 g_wl[W_TOTAL];
#define OFF_ENC1 0
#define OFF_ENC2 32768
#define OFF_GCN1 40960
#define OFF_GCN2 45056
#define OFF_DEC1 49152
#define OFF_DEC2 57344

// ---------------- weight splitting (runs once, tiny) ----------------
__global__ void k_splitw(const float* __restrict__ e1, const float* __restrict__ e2,
                         const float* __restrict__ g1, const float* __restrict__ g2,
                         const float* __restrict__ d1, const float* __restrict__ d2) {
    int i = blockIdx.x * blockDim.x + threadIdx.x;
    if (i >= W_TOTAL) return;
    float v;
    if      (i < OFF_ENC2) v = e1[i - OFF_ENC1];
    else if (i < OFF_GCN1) v = e2[i - OFF_ENC2];
    else if (i < OFF_GCN2) v = g1[i - OFF_GCN1];
    else if (i < OFF_DEC1) v = g2[i - OFF_GCN2];
    else if (i < OFF_DEC2) v = d1[i - OFF_DEC1];
    else                   v = d2[i - OFF_DEC2];
    __nv_bfloat16 h = __float2bfloat16(v);
    g_wh[i] = h;
    g_wl[i] = __float2bfloat16(v - __bfloat162float(h));
}

// ---------------- CSR build ----------------
__global__ void k_init_counts() {
    int i = blockIdx.x * blockDim.x + threadIdx.x;
    if (i < NN) { g_counts[i] = 0; g_cursor[i] = 0; g_degf[i] = 1.0f; }
}

__global__ void k_count(const int* __restrict__ dst, const float* __restrict__ w) {
    int e = blockIdx.x * blockDim.x + threadIdx.x;
    if (e < EE) {
        int d = dst[e];
        atomicAdd(&g_counts[d], 1);
        atomicAdd(&g_degf[d], w[e]);
    }
}

__global__ void k_dinv() {
    int i = blockIdx.x * blockDim.x + threadIdx.x;
    if (i < NN) g_dinv[i] = rsqrtf(g_degf[i]);
}

__global__ void k_scan1(int n) {
    __shared__ int warpsums[32];
    int tid = threadIdx.x;
    int lane = tid & 31, wid = tid >> 5;
    int i = blockIdx.x * 1024 + tid;
    int v = (i < n) ? g_counts[i] : 0;
    int incl = v;
    #pragma unroll
    for (int o = 1; o < 32; o <<= 1) {
        int t = __shfl_up_sync(0xffffffffu, incl, o);
        if (lane >= o) incl += t;
    }
    if (lane == 31) warpsums[wid] = incl;
    __syncthreads();
    if (wid == 0) {
        int ws = warpsums[lane];
        int wincl = ws;
        #pragma unroll
        for (int o = 1; o < 32; o <<= 1) {
            int t = __shfl_up_sync(0xffffffffu, wincl, o);
            if (lane >= o) wincl += t;
        }
        warpsums[lane] = wincl - ws;
        if (lane == 31) g_partials[blockIdx.x] = wincl;
    }
    __syncthreads();
    int excl = incl - v + warpsums[wid];
    if (i < n) g_rowptr[i] = excl;
}

__global__ void k_scan2(int nb, int n) {
    __shared__ int w0tot;
    int t = threadIdx.x;
    int lane = t & 31, w = t >> 5;
    int v = (t < nb) ? g_partials[t] : 0;
    int incl = v;
    #pragma unroll
    for (int o = 1; o < 32; o <<= 1) {
        int x = __shfl_up_sync(0xffffffffu, incl, o);
        if (lane >= o) incl += x;
    }
    if (w == 0 && lane == 31) w0tot = incl;
    __syncthreads();
    int base = (w == 1) ? w0tot : 0;
    int excl = base + incl - v;
    if (t < nb) g_partials[t] = excl;
    if (t == nb - 1) g_rowptr[n] = excl + v;
}

__global__ void k_scan3(int n) {
    int i = blockIdx.x * 1024 + threadIdx.x;
    if (i < n) g_rowptr[i] += g_partials[blockIdx.x];
}

__global__ void k_fill(const int* __restrict__ src,
                       const int* __restrict__ dst,
                       const float* __restrict__ w) {
    int e = blockIdx.x * blockDim.x + threadIdx.x;
    if (e >= EE) return;
    int d = dst[e];
    int s = src[e];
    int pos = atomicAdd(&g_cursor[d], 1);
    int p = g_rowptr[d] + pos;
    float coef = w[e] * g_dinv[s] * g_dinv[d];
    g_csr[p] = make_int2(s, __float_as_int(coef));
}

// ================== MMA helpers ==================
__device__ __forceinline__ uint32_t pack_bf16(__nv_bfloat16 a, __nv_bfloat16 b) {
    __nv_bfloat162 t(a, b);
    return *(uint32_t*)&t;
}

__device__ __forceinline__ void cvt_split(float4 v, uint2& hi, uint2& lo) {
    __nv_bfloat16 h0 = __float2bfloat16(v.x), h1 = __float2bfloat16(v.y);
    __nv_bfloat16 h2 = __float2bfloat16(v.z), h3 = __float2bfloat16(v.w);
    __nv_bfloat16 l0 = __float2bfloat16(v.x - __bfloat162float(h0));
    __nv_bfloat16 l1 = __float2bfloat16(v.y - __bfloat162float(h1));
    __nv_bfloat16 l2 = __float2bfloat16(v.z - __bfloat162float(h2));
    __nv_bfloat16 l3 = __float2bfloat16(v.w - __bfloat162float(h3));
    hi = make_uint2(pack_bf16(h0, h1), pack_bf16(h2, h3));
    lo = make_uint2(pack_bf16(l0, l1), pack_bf16(l2, l3));
}

__device__ __forceinline__ uint32_t pk(float v) {
    __nv_bfloat16 h = __float2bfloat16(v);
    __nv_bfloat16 l = __float2bfloat16(v - __bfloat162float(h));
    return (uint32_t)*(uint16_t*)&h | ((uint32_t)*(uint16_t*)&l << 16);
}

__device__ __forceinline__ void prmt_split(uint4 p, uint2& hi, uint2& lo) {
    hi.x = __byte_perm(p.x, p.y, 0x5410);
    hi.y = __byte_perm(p.z, p.w, 0x5410);
    lo.x = __byte_perm(p.x, p.y, 0x7632);
    lo.y = __byte_perm(p.z, p.w, 0x7632);
}

__device__ __forceinline__ void split2(float a, float b, uint32_t& hi, uint32_t& lo) {
    __nv_bfloat16 h0 = __float2bfloat16(a), h1 = __float2bfloat16(b);
    __nv_bfloat16 l0 = __float2bfloat16(a - __bfloat162float(h0));
    __nv_bfloat16 l1 = __float2bfloat16(b - __bfloat162float(h1));
    hi = pack_bf16(h0, h1);
    lo = pack_bf16(l0, l1);
}

#define MMA_BF16(c, a, b0v, b1v) \
    asm volatile("mma.sync.aligned.m16n8k16.row.col.f32.bf16.bf16.f32 " \
        "{%0,%1,%2,%3}, {%4,%5,%6,%7}, {%8,%9}, {%0,%1,%2,%3};" \
        : "+f"((c)[0]), "+f"((c)[1]), "+f"((c)[2]), "+f"((c)[3]) \
        : "r"((a)[0]), "r"((a)[1]), "r"((a)[2]), "r"((a)[3]), "r"(b0v), "r"(b1v))

__device__ __forceinline__ void apply_epi(int EPI, float& v) {
    if (EPI == 1) v = fmaxf(v, 0.f);
    if (EPI == 2) v = 1.0f / (1.0f + __expf(-v));
}

// ================== standalone warp-MMA GEMM (double-buffered, R11 layout) ==================
// AP: A format (0=fp32 convert, 1=packed hi/lo).  OP: output (0=fp32, 1=packed, 2=fp16).
template <int BN, int EPI, int AP, int OP>
__global__ void __launch_bounds__(256)
k_mma(const void* __restrict__ Av, const __nv_bfloat16* __restrict__ Bh_g,
      const __nv_bfloat16* __restrict__ Bl_g,
      const float* __restrict__ bias, void* __restrict__ Cv,
      int M, int N, int K) {
    constexpr int BM = 128, BK = 32, SKP = 40;
    constexpr int NI = BN / 16;
    constexpr int ASZ = BM * SKP;
    constexpr int BSZ = BN * SKP;
    constexpr int BUF = 2 * ASZ + 2 * BSZ;
    extern __shared__ __nv_bfloat16 dsm[];

    const int tid = threadIdx.x;
    const int wid = tid >> 5, lane = tid & 31;
    const int g = lane >> 2, tc = lane & 3;
    const int wm = wid >> 1, wn = wid & 1;
    const int bm = blockIdx.y * BM, bn = blockIdx.x * BN;

    constexpr int AL = (BM * 8) / 256;
    constexpr int BL = (BN * 8) / 256;
    uint4 ra[AL];
    uint2 rbh[BL], rbl[BL];

    float acc[2][NI][4];
    #pragma unroll
    for (int mi = 0; mi < 2; ++mi)
        #pragma unroll
        for (int ni = 0; ni < NI; ++ni)
            #pragma unroll
            for (int j = 0; j < 4; ++j) acc[mi][ni][j] = 0.0f;

    auto load_regs = [&](int kt) {
        const int k0 = kt * BK;
        #pragma unroll
        for (int l = 0; l < AL; ++l) {
            int idx = tid + l * 256;
            int r = idx >> 3, c4 = (idx & 7) * 4;
            ra[l] = (bm + r < M)
                ? *(const uint4*)((const uint32_t*)Av + (size_t)(bm + r) * K + k0 + c4)
                : make_uint4(0u, 0u, 0u, 0u);
        }
        #pragma unroll
        for (int l = 0; l < BL; ++l) {
            int idx = tid + l * 256;
            int r = idx >> 3, c4 = (idx & 7) * 4;
            size_t off = (size_t)(bn + r) * K + k0 + c4;
            rbh[l] = *(const uint2*)(Bh_g + off);
            rbl[l] = *(const uint2*)(Bl_g + off);
        }
    };
    auto store_smem = [&](int buf) {
        __nv_bfloat16* Ah = dsm + buf * BUF;
        __nv_bfloat16* Al = Ah + ASZ;
        __nv_bfloat16* Bh = Al + ASZ;
        __nv_bfloat16* Bl = Bh + BSZ;
        #pragma unroll
        for (int l = 0; l < AL; ++l) {
            int idx = tid + l * 256;
            int r = idx >> 3, c4 = (idx & 7) * 4;
            uint2 hi, lo;
            if (AP) prmt_split(ra[l], hi, lo);
            else    cvt_split(*(float4*)&ra[l], hi, lo);
            *(uint2*)&Ah[r * SKP + c4] = hi;
            *(uint2*)&Al[r * SKP + c4] = lo;
        }
        #pragma unroll
        for (int l = 0; l < BL; ++l) {
            int idx = tid + l * 256;
            int r = idx >> 3, c4 = (idx & 7) * 4;
            *(uint2*)&Bh[r * SKP + c4] = rbh[l];
            *(uint2*)&Bl[r * SKP + c4] = rbl[l];
        }
    };
    auto compute = [&](int buf) {
        const __nv_bfloat16* Ah = dsm + buf * BUF;
        const __nv_bfloat16* Al = Ah + ASZ;
        const __nv_bfloat16* Bh = Al + ASZ;
        const __nv_bfloat16* Bl = Bh + BSZ;
        #pragma unroll
        for (int ks = 0; ks < BK; ks += 16) {
            uint32_t ah[2][4], al[2][4];
            #pragma unroll
            for (int mi = 0; mi < 2; ++mi) {
                int rb_ = wm * 32 + mi * 16 + g;
                const __nv_bfloat16* ph = &Ah[rb_ * SKP + ks + 2 * tc];
                ah[mi][0] = *(const uint32_t*)ph;
                ah[mi][1] = *(const uint32_t*)(ph + 8 * SKP);
                ah[mi][2] = *(const uint32_t*)(ph + 8);
                ah[mi][3] = *(const uint32_t*)(ph + 8 * SKP + 8);
                const __nv_bfloat16* pl = &Al[rb_ * SKP + ks + 2 * tc];
                al[mi][0] = *(const uint32_t*)pl;
                al[mi][1] = *(const uint32_t*)(pl + 8 * SKP);
                al[mi][2] = *(const uint32_t*)(pl + 8);
                al[mi][3] = *(const uint32_t*)(pl + 8 * SKP + 8);
            }
            #pragma unroll
            for (int ni = 0; ni < NI; ++ni) {
                int nb = wn * (BN / 2) + ni * 8 + g;
                const __nv_bfloat16* pbh = &Bh[nb * SKP + ks + 2 * tc];
                uint32_t bh0 = *(const uint32_t*)pbh;
                uint32_t bh1 = *(const uint32_t*)(pbh + 8);
                const __nv_bfloat16* pbl = &Bl[nb * SKP + ks + 2 * tc];
                uint32_t bl0 = *(const uint32_t*)pbl;
                uint32_t bl1 = *(const uint32_t*)(pbl + 8);
                #pragma unroll
                for (int mi = 0; mi < 2; ++mi) {
                    MMA_BF16(acc[mi][ni], ah[mi], bh0, bh1);
                    MMA_BF16(acc[mi][ni], ah[mi], bl0, bl1);
                    MMA_BF16(acc[mi][ni], al[mi], bh0, bh1);
                }
            }
        }
    };

    load_regs(0);
    store_smem(0);
    __syncthreads();
    const int nk = K / BK;
    for (int kt = 0; kt < nk; ++kt) {
        if (kt + 1 < nk) load_regs(kt + 1);
        compute(kt & 1);
        if (kt + 1 < nk) store_smem((kt + 1) & 1);
        __syncthreads();
    }

    #pragma unroll
    for (int ni = 0; ni < NI; ++ni) {
        int n0 = bn + wn * (BN / 2) + ni * 8 + 2 * tc;
        float b0 = 0.f, b1 = 0.f;
        if (EPI >= 1) { b0 = __ldg(&bias[n0]); b1 = __ldg(&bias[n0 + 1]); }
        #pragma unroll
        for (int mi = 0; mi < 2; ++mi) {
            int m0 = bm + wm * 32 + mi * 16 + g;
            float v0 = acc[mi][ni][0] + b0, v1 = acc[mi][ni][1] + b1;
            float v2 = acc[mi][ni][2] + b0, v3 = acc[mi][ni][3] + b1;
            apply_epi(EPI, v0); apply_epi(EPI, v1); apply_epi(EPI, v2); apply_epi(EPI, v3);
            if (OP == 1) {
                if (m0 < M)     *(uint2*)((uint32_t*)Cv + (size_t)m0 * N + n0)       = make_uint2(pk(v0), pk(v1));
                if (m0 + 8 < M) *(uint2*)((uint32_t*)Cv + (size_t)(m0 + 8) * N + n0) = make_uint2(pk(v2), pk(v3));
            } else if (OP == 2) {
                __half2* H = (__half2*)Cv;
                if (m0 < M)     H[((size_t)m0 * N + n0) >> 1]       = __floats2half2_rn(v0, v1);
                if (m0 + 8 < M) H[((size_t)(m0 + 8) * N + n0) >> 1] = __floats2half2_rn(v2, v3);
            } else {
                if (m0 < M)     *(float2*)((float*)Cv + (size_t)m0 * N + n0)       = make_float2(v0, v1);
                if (m0 + 8 < M) *(float2*)((float*)Cv + (size_t)(m0 + 8) * N + n0) = make_float2(v2, v3);
            }
        }
    }
}

// ================== fused 2-layer GEMM (A packed, B pre-split; R11 layout) ==================
// OC: stage-2 output format (0=fp32, 2=fp16)
template <int K1, int N1, int N2, int EPI2, int OC>
__global__ void __launch_bounds__(256)
k_fused(const uint32_t* __restrict__ A,
        const __nv_bfloat16* __restrict__ B1h, const __nv_bfloat16* __restrict__ B1l,
        const float* __restrict__ b1,
        const __nv_bfloat16* __restrict__ B2h, const __nv_bfloat16* __restrict__ B2l,
        const float* __restrict__ b2, void* __restrict__ C, int M) {
    constexpr int BM = 128, BK = 32, SKP = 40;
    constexpr int TSKP = N1 + 8;
    constexpr int NI1 = N1 / 16;
    constexpr int BN2 = (N2 > 128) ? 128 : N2;
    constexpr int NI2 = BN2 / 16;
    constexpr int NH = N2 / BN2;
    constexpr int BNMAX = (N1 > BN2) ? N1 : BN2;
    constexpr int ASZ = BM * SKP;
    constexpr int BSZ = BNMAX * SKP;
    extern __shared__ __nv_bfloat16 dsm[];
    __nv_bfloat16* Ah = dsm;
    __nv_bfloat16* Al = Ah + ASZ;
    __nv_bfloat16* Bh = Al + ASZ;
    __nv_bfloat16* Bl = Bh + BSZ;
    __nv_bfloat16* Th = Bl + BSZ;
    __nv_bfloat16* Tl = Th + BM * TSKP;

    const int tid = threadIdx.x;
    const int wid = tid >> 5, lane = tid & 31;
    const int g = lane >> 2, tc = lane & 3;
    const int wm = wid >> 1, wn = wid & 1;
    const int bm = blockIdx.y * BM;

    // ---------- stage 1 ----------
    {
        float acc[2][NI1][4];
        #pragma unroll
        for (int mi = 0; mi < 2; ++mi)
            #pragma unroll
            for (int ni = 0; ni < NI1; ++ni)
                #pragma unroll
                for (int j = 0; j < 4; ++j) acc[mi][ni][j] = 0.0f;

        for (int kt = 0; kt < K1 / BK; ++kt) {
            const int k0 = kt * BK;
            if (kt > 0) __syncthreads();
            #pragma unroll
            for (int l = 0; l < (BM * 8) / 256; ++l) {
                int idx = tid + l * 256;
                int r = idx >> 3, c4 = (idx & 7) * 4;
                uint4 p = (bm + r < M) ? *(const uint4*)(A + (size_t)(bm + r) * K1 + k0 + c4)
                                       : make_uint4(0u, 0u, 0u, 0u);
                uint2 hi, lo; prmt_split(p, hi, lo);
                *(uint2*)&Ah[r * SKP + c4] = hi;
                *(uint2*)&Al[r * SKP + c4] = lo;
            }
            #pragma unroll
            for (int l = 0; l < (N1 * 8) / 256; ++l) {
                int idx = tid + l * 256;
                int r = idx >> 3, c4 = (idx & 7) * 4;
                size_t off = (size_t)r * K1 + k0 + c4;
                *(uint2*)&Bh[r * SKP + c4] = *(const uint2*)(B1h + off);
                *(uint2*)&Bl[r * SKP + c4] = *(const uint2*)(B1l + off);
            }
            __syncthreads();
            #pragma unroll
            for (int ks = 0; ks < BK; ks += 16) {
                uint32_t ah[2][4], al[2][4];
                #pragma unroll
                for (int mi = 0; mi < 2; ++mi) {
                    int rb_ = wm * 32 + mi * 16 + g;
                    const __nv_bfloat16* ph = &Ah[rb_ * SKP + ks + 2 * tc];
                    ah[mi][0] = *(const uint32_t*)ph;
                    ah[mi][1] = *(const uint32_t*)(ph + 8 * SKP);
                    ah[mi][2] = *(const uint32_t*)(ph + 8);
                    ah[mi][3] = *(const uint32_t*)(ph + 8 * SKP + 8);
                    const __nv_bfloat16* pl = &Al[rb_ * SKP + ks + 2 * tc];
                    al[mi][0] = *(const uint32_t*)pl;
                    al[mi][1] = *(const uint32_t*)(pl + 8 * SKP);
                    al[mi][2] = *(const uint32_t*)(pl + 8);
                    al[mi][3] = *(const uint32_t*)(pl + 8 * SKP + 8);
                }
                #pragma unroll
                for (int ni = 0; ni < NI1; ++ni) {
                    int nb = wn * (N1 / 2) + ni * 8 + g;
                    const __nv_bfloat16* pbh = &Bh[nb * SKP + ks + 2 * tc];
                    uint32_t bh0 = *(const uint32_t*)pbh;
                    uint32_t bh1 = *(const uint32_t*)(pbh + 8);
                    const __nv_bfloat16* pbl = &Bl[nb * SKP + ks + 2 * tc];
                    uint32_t bl0 = *(const uint32_t*)pbl;
                    uint32_t bl1 = *(const uint32_t*)(pbl + 8);
                    #pragma unroll
                    for (int mi = 0; mi < 2; ++mi) {
                        MMA_BF16(acc[mi][ni], ah[mi], bh0, bh1);
                        MMA_BF16(acc[mi][ni], ah[mi], bl0, bl1);
                        MMA_BF16(acc[mi][ni], al[mi], bh0, bh1);
                    }
                }
            }
        }
        __syncthreads();
        #pragma unroll
        for (int ni = 0; ni < NI1; ++ni) {
            int n0 = wn * (N1 / 2) + ni * 8 + 2 * tc;
            float b0 = __ldg(&b1[n0]), b1v = __ldg(&b1[n0 + 1]);
            #pragma unroll
            for (int mi = 0; mi < 2; ++mi) {
                int r0 = wm * 32 + mi * 16 + g;
                float v0 = fmaxf(acc[mi][ni][0] + b0, 0.f);
                float v1 = fmaxf(acc[mi][ni][1] + b1v, 0.f);
                float v2 = fmaxf(acc[mi][ni][2] + b0, 0.f);
                float v3 = fmaxf(acc[mi][ni][3] + b1v, 0.f);
                uint32_t hi, lo;
                split2(v0, v1, hi, lo);
                *(uint32_t*)&Th[r0 * TSKP + n0] = hi;
                *(uint32_t*)&Tl[r0 * TSKP + n0] = lo;
                split2(v2, v3, hi, lo);
                *(uint32_t*)&Th[(r0 + 8) * TSKP + n0] = hi;
                *(uint32_t*)&Tl[(r0 + 8) * TSKP + n0] = lo;
            }
        }
        __syncthreads();
    }

    // ---------- stage 2 ----------
    for (int h = 0; h < NH; ++h) {
        const int nbase = h * BN2;
        float acc[2][NI2][4];
        #pragma unroll
        for (int mi = 0; mi < 2; ++mi)
            #pragma unroll
            for (int ni = 0; ni < NI2; ++ni)
                #pragma unroll
                for (int j = 0; j < 4; ++j) acc[mi][ni][j] = 0.0f;

        for (int kt = 0; kt < N1 / BK; ++kt) {
            const int k0 = kt * BK;
            if (h > 0 || kt > 0) __syncthreads();
            #pragma unroll
            for (int l = 0; l < (BN2 * 8) / 256; ++l) {
                int idx = tid + l * 256;
                int r = idx >> 3, c4 = (idx & 7) * 4;
                size_t off = (size_t)(nbase + r) * N1 + k0 + c4;
                *(uint2*)&Bh[r * SKP + c4] = *(const uint2*)(B2h + off);
                *(uint2*)&Bl[r * SKP + c4] = *(const uint2*)(B2l + off);
            }
            __syncthreads();
            #pragma unroll
            for (int ks = 0; ks < BK; ks += 16) {
                const int kk = k0 + ks;
                uint32_t ah[2][4], al[2][4];
                #pragma unroll
                for (int mi = 0; mi < 2; ++mi) {
                    int rb_ = wm * 32 + mi * 16 + g;
                    const __nv_bfloat16* ph = &Th[rb_ * TSKP + kk + 2 * tc];
                    ah[mi][0] = *(const uint32_t*)ph;
                    ah[mi][1] = *(const uint32_t*)(ph + 8 * TSKP);
                    ah[mi][2] = *(const uint32_t*)(ph + 8);
                    ah[mi][3] = *(const uint32_t*)(ph + 8 * TSKP + 8);
                    const __nv_bfloat16* pl = &Tl[rb_ * TSKP + kk + 2 * tc];
                    al[mi][0] = *(const uint32_t*)pl;
                    al[mi][1] = *(const uint32_t*)(pl + 8 * TSKP);
                    al[mi][2] = *(const uint32_t*)(pl + 8);
                    al[mi][3] = *(const uint32_t*)(pl + 8 * TSKP + 8);
                }
                #pragma unroll
                for (int ni = 0; ni < NI2; ++ni) {
                    int nb = wn * (BN2 / 2) + ni * 8 + g;
                    const __nv_bfloat16* pbh = &Bh[nb * SKP + ks + 2 * tc];
                    uint32_t bh0 = *(const uint32_t*)pbh;
                    uint32_t bh1 = *(const uint32_t*)(pbh + 8);
                    const __nv_bfloat16* pbl = &Bl[nb * SKP + ks + 2 * tc];
                    uint32_t bl0 = *(const uint32_t*)pbl;
                    uint32_t bl1 = *(const uint32_t*)(pbl + 8);
                    #pragma unroll
                    for (int mi = 0; mi < 2; ++mi) {
                        MMA_BF16(acc[mi][ni], ah[mi], bh0, bh1);
                        MMA_BF16(acc[mi][ni], ah[mi], bl0, bl1);
                        MMA_BF16(acc[mi][ni], al[mi], bh0, bh1);
                    }
                }
            }
        }
        #pragma unroll
        for (int ni = 0; ni < NI2; ++ni) {
            int nl = wn * (BN2 / 2) + ni * 8 + 2 * tc;
            int n0 = nbase + nl;
            float b0 = 0.f, b1v = 0.f;
            if (EPI2 >= 1) { b0 = __ldg(&b2[n0]); b1v = __ldg(&b2[n0 + 1]); }
            #pragma unroll
            for (int mi = 0; mi < 2; ++mi) {
                int m0 = bm + wm * 32 + mi * 16 + g;
                float v0 = acc[mi][ni][0] + b0, v1 = acc[mi][ni][1] + b1v;
                float v2 = acc[mi][ni][2] + b0, v3 = acc[mi][ni][3] + b1v;
                apply_epi(EPI2, v0); apply_epi(EPI2, v1);
                apply_epi(EPI2, v2); apply_epi(EPI2, v3);
                if (OC == 2) {
                    __half2* H = (__half2*)C;
                    if (m0 < M)     H[((size_t)m0 * N2 + n0) >> 1]       = __floats2half2_rn(v0, v1);
                    if (m0 + 8 < M) H[((size_t)(m0 + 8) * N2 + n0) >> 1] = __floats2half2_rn(v2, v3);
                } else {
                    float* F = (float*)C;
                    if (m0 < M)     *(float2*)&F[(size_t)m0 * N2 + n0]       = make_float2(v0, v1);
                    if (m0 + 8 < M) *(float2*)&F[(size_t)(m0 + 8) * N2 + n0] = make_float2(v2, v3);
                }
            }
        }
    }
}

// ---------------- SpMM aggregation (pull, warp per node, fp16 gather, packed out) ----------------
__global__ void __launch_bounds__(256)
k_spmm(const __half2* __restrict__ hw, const float* __restrict__ bias,
       uint32_t* __restrict__ out) {
    int warp = (blockIdx.x * blockDim.x + threadIdx.x) >> 5;
    int lane = threadIdx.x & 31;
    if (warp >= NN) return;
    int node = warp;
    float dinv_i = g_dinv[node];
    float selfc = dinv_i * dinv_i;

    float2 hv0 = __half22float2(hw[(size_t)node * 32 + lane]);
    float accx = selfc * hv0.x;
    float accy = selfc * hv0.y;

    int start = g_rowptr[node], end = g_rowptr[node + 1];
    for (int base = start; base < end; base += 32) {
        int p = base + lane;
        int s = 0; float c = 0.0f;
        if (p < end) {
            int2 e = g_csr[p];
            s = e.x;
            c = __int_as_float(e.y);
        }
        #pragma unroll
        for (int j = 0; j < 32; ++j) {
            float cj = __shfl_sync(0xffffffffu, c, j);
            int   sj = __shfl_sync(0xffffffffu, s, j);
            if (cj != 0.0f) {
                float2 hv = __half22float2(hw[(size_t)sj * 32 + lane]);
                accx += cj * hv.x;
                accy += cj * hv.y;
            }
        }
    }
    float bx = bias[lane * 2], by = bias[lane * 2 + 1];
    float ox = fmaxf(accx + bx, 0.0f);
    float oy = fmaxf(accy + by, 0.0f);
    *(uint2*)&out[(size_t)node * D_H2 + lane * 2] = make_uint2(pk(ox), pk(oy));
}

// ---------------- launch ----------------
extern "C" void kernel_launch(void* const* d_in, const int* in_sizes, int n_in,
                              void* d_out, int out_size) {
    const float* x  = (const float*)d_in[0];
    const int*   ei = (const int*)d_in[1];      // int32 (JAX x64 disabled)
    const float* ew = (const float*)d_in[2];
    const float* enc1_w = (const float*)d_in[3];
    const float* enc1_b = (const float*)d_in[4];
    const float* enc2_w = (const float*)d_in[5];
    const float* enc2_b = (const float*)d_in[6];
    const float* gcn1_w = (const float*)d_in[7];
    const float* gcn1_b = (const float*)d_in[8];
    const float* gcn2_w = (const float*)d_in[9];
    const float* gcn2_b = (const float*)d_in[10];
    const float* dec1_w = (const float*)d_in[11];
    const float* dec1_b = (const float*)d_in[12];
    const float* dec2_w = (const float*)d_in[13];
    const float* dec2_b = (const float*)d_in[14];
    float* out = (float*)d_out;

    const int* srcp = ei;
    const int* dstp = ei + EE;

    uint32_t *h1, *h2, *g;
    __half *hw;
    cudaGetSymbolAddress((void**)&h1, g_h1);
    cudaGetSymbolAddress((void**)&h2, g_h2);
    cudaGetSymbolAddress((void**)&hw, g_hw);
    cudaGetSymbolAddress((void**)&g,  g_g);
    __nv_bfloat16 *wh, *wl;
    cudaGetSymbolAddress((void**)&wh, g_wh);
    cudaGetSymbolAddress((void**)&wl, g_wl);

    // dynamic smem sizes (bytes) — R11 tile layout
    const int SM128  = 2 * (2 * 128 * 40 + 2 * 128 * 40) * 2;               // 81920
    const int SM64   = 2 * (2 * 128 * 40 + 2 * 64 * 40) * 2;                // 61440
    const int SMF_E  = (2 * 128 * 40 + 2 * 64 * 40 + 2 * 128 * 72) * 2;     // 67584
    const int SMF_D  = (2 * 128 * 40 + 2 * 128 * 40 + 2 * 128 * 136) * 2;   // 110592
    cudaFuncSetAttribute(k_mma<128, 1, 0, 1>, cudaFuncAttributeMaxDynamicSharedMemorySize, SM128);
    cudaFuncSetAttribute(k_mma<64, 0, 1, 2>,  cudaFuncAttributeMaxDynamicSharedMemorySize, SM64);
    cudaFuncSetAttribute(k_fused<128, 64, 64, 0, 2>,  cudaFuncAttributeMaxDynamicSharedMemorySize, SMF_E);
    cudaFuncSetAttribute(k_fused<64, 128, 256, 2, 0>, cudaFuncAttributeMaxDynamicSharedMemorySize, SMF_D);

    const int TB = 256;
    int gridN = (NN + TB - 1) / TB;
    int gridE = (EE + TB - 1) / TB;
    const int NB = (NN + 1023) / 1024;

    // ---- fork: CSR build on a side stream ----
    cudaStream_t side;
    cudaStreamCreateWithFlags(&side, cudaStreamNonBlocking);
    cudaEvent_t e0, e1;
    cudaEventCreateWithFlags(&e0, cudaEventDisableTiming);
    cudaEventCreateWithFlags(&e1, cudaEventDisableTiming);

    cudaEventRecord(e0, 0);
    cudaStreamWaitEvent(side, e0, 0);
    k_init_counts<<<gridN, TB, 0, side>>>();
    k_count<<<gridE, TB, 0, side>>>(dstp, ew);
    k_dinv<<<gridN, TB, 0, side>>>();
    k_scan1<<<NB, 1024, 0, side>>>(NN);
    k_scan2<<<1, 64, 0, side>>>(NB, NN);
    k_scan3<<<NB, 1024, 0, side>>>(NN);
    k_fill<<<gridE, TB, 0, side>>>(srcp, dstp, ew);
    cudaEventRecord(e1, side);

    const int MY = (NN + 127) / 128;   // 391

    // main stream: split weights, enc1 (BN=128, champion config), fused enc2+gcn1-matmul
    k_splitw<<<(W_TOTAL + 255) / 256, 256>>>(enc1_w, enc2_w, gcn1_w, gcn2_w, dec1_w, dec2_w);
    k_mma<128, 1, 0, 1><<<dim3(1, MY), 256, SM128>>>(x, wh + OFF_ENC1, wl + OFF_ENC1,
                                                     enc1_b, h1, NN, D_H1, D_IN);
    k_fused<128, 64, 64, 0, 2><<<dim3(1, MY), 256, SMF_E>>>(h1, wh + OFF_ENC2, wl + OFF_ENC2,
                                                            enc2_b, wh + OFF_GCN1, wl + OFF_GCN1,
                                                            nullptr, hw, NN);

    // ---- join: aggregation needs the CSR ----
    cudaStreamWaitEvent(0, e1, 0);
    k_spmm<<<(NN * 32 + TB - 1) / TB, TB>>>((const __half2*)hw, gcn1_b, g);
    k_mma<64, 0, 1, 2><<<dim3(1, MY), 256, SM64>>>(g, wh + OFF_GCN2, wl + OFF_GCN2,
                                                   nullptr, hw, NN, D_H2, D_H2);
    k_spmm<<<(NN * 32 + TB - 1) / TB, TB>>>((const __half2*)hw, gcn2_b, h2);

    // fused dec1+dec2 (bias+relu, then bias+sigmoid)
    k_fused<64, 128, 256, 2, 0><<<dim3(1, MY), 256, SMF_D>>>(h2, wh + OFF_DEC1, wl + OFF_DEC1,
                                                             dec1_b, wh + OFF_DEC2, wl + OFF_DEC2,
                                                             dec2_b, out, NN);
    // note: side stream + events intentionally not destroyed (capture-safe; few calls)
}

// round 17
// speedup vs baseline: 1.0973x; 1.0973x over previous
#include <cuda_runtime.h>
#include <cuda_bf16.h>
#include <math.h>
#include <stdint.h>

// Problem constants (fixed by the dataset)
#define NN 50000
#define EE 1600000
#define D_IN 256
#define D_H1 128
#define D_H2 64

// ---------------- scratch (static device globals; no allocation) ----------------
static __device__ __align__(16) uint32_t g_h1[(size_t)NN * D_H1];  // packed hi/lo
static __device__ __align__(16) uint32_t g_h2[(size_t)NN * D_H2];  // packed hi/lo
static __device__ __align__(16) float    g_hw[(size_t)NN * D_H2];  // fp32 (spmm gathers)
static __device__ __align__(16) uint32_t g_g [(size_t)NN * D_H2];  // packed hi/lo
static __device__ float g_dinv[NN];
static __device__ float g_degf[NN];
static __device__ int   g_counts[NN];
static __device__ int   g_cursor[NN];
static __device__ int   g_rowptr[NN + 1];
static __device__ int   g_partials[64];
static __device__ __align__(8) int2 g_csr[EE];   // .x = src, .y = float bits of coeff

// pre-split weights (hi/lo bf16), concatenated
#define W_TOTAL 90112
static __device__ __align__(16) __nv_bfloat16 g_wh[W_TOTAL];
static __device__ __align__(16) __nv_bfloat16 g_wl[W_TOTAL];
#define OFF_ENC1 0
#define OFF_ENC2 32768
#define OFF_GCN1 40960
#define OFF_GCN2 45056
#define OFF_DEC1 49152
#define OFF_DEC2 57344

// ---------------- weight splitting (runs once, tiny) ----------------
__global__ void k_splitw(const float* __restrict__ e1, const float* __restrict__ e2,
                         const float* __restrict__ g1, const float* __restrict__ g2,
                         const float* __restrict__ d1, const float* __restrict__ d2) {
    int i = blockIdx.x * blockDim.x + threadIdx.x;
    if (i >= W_TOTAL) return;
    float v;
    if      (i < OFF_ENC2) v = e1[i - OFF_ENC1];
    else if (i < OFF_GCN1) v = e2[i - OFF_ENC2];
    else if (i < OFF_GCN2) v = g1[i - OFF_GCN1];
    else if (i < OFF_DEC1) v = g2[i - OFF_GCN2];
    else if (i < OFF_DEC2) v = d1[i - OFF_DEC1];
    else                   v = d2[i - OFF_DEC2];
    __nv_bfloat16 h = __float2bfloat16(v);
    g_wh[i] = h;
    g_wl[i] = __float2bfloat16(v - __bfloat162float(h));
}

// ---------------- CSR build ----------------
__global__ void k_init_counts() {
    int i = blockIdx.x * blockDim.x + threadIdx.x;
    if (i < NN) { g_counts[i] = 0; g_cursor[i] = 0; g_degf[i] = 1.0f; }
}

__global__ void k_count(const int* __restrict__ dst, const float* __restrict__ w) {
    int e = blockIdx.x * blockDim.x + threadIdx.x;
    if (e < EE) {
        int d = dst[e];
        atomicAdd(&g_counts[d], 1);
        atomicAdd(&g_degf[d], w[e]);
    }
}

__global__ void k_dinv() {
    int i = blockIdx.x * blockDim.x + threadIdx.x;
    if (i < NN) g_dinv[i] = rsqrtf(g_degf[i]);
}

__global__ void k_scan1(int n) {
    __shared__ int warpsums[32];
    int tid = threadIdx.x;
    int lane = tid & 31, wid = tid >> 5;
    int i = blockIdx.x * 1024 + tid;
    int v = (i < n) ? g_counts[i] : 0;
    int incl = v;
    #pragma unroll
    for (int o = 1; o < 32; o <<= 1) {
        int t = __shfl_up_sync(0xffffffffu, incl, o);
        if (lane >= o) incl += t;
    }
    if (lane == 31) warpsums[wid] = incl;
    __syncthreads();
    if (wid == 0) {
        int ws = warpsums[lane];
        int wincl = ws;
        #pragma unroll
        for (int o = 1; o < 32; o <<= 1) {
            int t = __shfl_up_sync(0xffffffffu, wincl, o);
            if (lane >= o) wincl += t;
        }
        warpsums[lane] = wincl - ws;
        if (lane == 31) g_partials[blockIdx.x] = wincl;
    }
    __syncthreads();
    int excl = incl - v + warpsums[wid];
    if (i < n) g_rowptr[i] = excl;
}

__global__ void k_scan2(int nb, int n) {
    __shared__ int w0tot;
    int t = threadIdx.x;
    int lane = t & 31, w = t >> 5;
    int v = (t < nb) ? g_partials[t] : 0;
    int incl = v;
    #pragma unroll
    for (int o = 1; o < 32; o <<= 1) {
        int x = __shfl_up_sync(0xffffffffu, incl, o);
        if (lane >= o) incl += x;
    }
    if (w == 0 && lane == 31) w0tot = incl;
    __syncthreads();
    int base = (w == 1) ? w0tot : 0;
    int excl = base + incl - v;
    if (t < nb) g_partials[t] = excl;
    if (t == nb - 1) g_rowptr[n] = excl + v;
}

__global__ void k_scan3(int n) {
    int i = blockIdx.x * 1024 + threadIdx.x;
    if (i < n) g_rowptr[i] += g_partials[blockIdx.x];
}

__global__ void k_fill(const int* __restrict__ src,
                       const int* __restrict__ dst,
                       const float* __restrict__ w) {
    int e = blockIdx.x * blockDim.x + threadIdx.x;
    if (e >= EE) return;
    int d = dst[e];
    int s = src[e];
    int pos = atomicAdd(&g_cursor[d], 1);
    int p = g_rowptr[d] + pos;
    float coef = w[e] * g_dinv[s] * g_dinv[d];
    g_csr[p] = make_int2(s, __float_as_int(coef));
}

// ================== MMA helpers ==================
__device__ __forceinline__ uint32_t pack_bf16(__nv_bfloat16 a, __nv_bfloat16 b) {
    __nv_bfloat162 t(a, b);
    return *(uint32_t*)&t;
}

__device__ __forceinline__ void cvt_split(float4 v, uint2& hi, uint2& lo) {
    __nv_bfloat16 h0 = __float2bfloat16(v.x), h1 = __float2bfloat16(v.y);
    __nv_bfloat16 h2 = __float2bfloat16(v.z), h3 = __float2bfloat16(v.w);
    __nv_bfloat16 l0 = __float2bfloat16(v.x - __bfloat162float(h0));
    __nv_bfloat16 l1 = __float2bfloat16(v.y - __bfloat162float(h1));
    __nv_bfloat16 l2 = __float2bfloat16(v.z - __bfloat162float(h2));
    __nv_bfloat16 l3 = __float2bfloat16(v.w - __bfloat162float(h3));
    hi = make_uint2(pack_bf16(h0, h1), pack_bf16(h2, h3));
    lo = make_uint2(pack_bf16(l0, l1), pack_bf16(l2, l3));
}

__device__ __forceinline__ uint32_t pk(float v) {
    __nv_bfloat16 h = __float2bfloat16(v);
    __nv_bfloat16 l = __float2bfloat16(v - __bfloat162float(h));
    return (uint32_t)*(uint16_t*)&h | ((uint32_t)*(uint16_t*)&l << 16);
}

__device__ __forceinline__ void prmt_split(uint4 p, uint2& hi, uint2& lo) {
    hi.x = __byte_perm(p.x, p.y, 0x5410);
    hi.y = __byte_perm(p.z, p.w, 0x5410);
    lo.x = __byte_perm(p.x, p.y, 0x7632);
    lo.y = __byte_perm(p.z, p.w, 0x7632);
}

__device__ __forceinline__ void split2(float a, float b, uint32_t& hi, uint32_t& lo) {
    __nv_bfloat16 h0 = __float2bfloat16(a), h1 = __float2bfloat16(b);
    __nv_bfloat16 l0 = __float2bfloat16(a - __bfloat162float(h0));
    __nv_bfloat16 l1 = __float2bfloat16(b - __bfloat162float(h1));
    hi = pack_bf16(h0, h1);
    lo = pack_bf16(l0, l1);
}

#define MMA_BF16(c, a, b0v, b1v) \
    asm volatile("mma.sync.aligned.m16n8k16.row.col.f32.bf16.bf16.f32 " \
        "{%0,%1,%2,%3}, {%4,%5,%6,%7}, {%8,%9}, {%0,%1,%2,%3};" \
        : "+f"((c)[0]), "+f"((c)[1]), "+f"((c)[2]), "+f"((c)[3]) \
        : "r"((a)[0]), "r"((a)[1]), "r"((a)[2]), "r"((a)[3]), "r"(b0v), "r"(b1v))

__device__ __forceinline__ void apply_epi(int EPI, float& v) {
    if (EPI == 1) v = fmaxf(v, 0.f);
    if (EPI == 2) v = 1.0f / (1.0f + __expf(-v));
}

// ================== standalone warp-MMA GEMM (double-buffered, R11 layout) ==================
// AP: A format (0=fp32 convert, 1=packed hi/lo).  OP: output (0=fp32, 1=packed).
template <int BN, int EPI, int AP, int OP>
__global__ void __launch_bounds__(256)
k_mma(const void* __restrict__ Av, const __nv_bfloat16* __restrict__ Bh_g,
      const __nv_bfloat16* __restrict__ Bl_g,
      const float* __restrict__ bias, void* __restrict__ Cv,
      int M, int N, int K) {
    constexpr int BM = 128, BK = 32, SKP = 40;
    constexpr int NI = BN / 16;
    constexpr int ASZ = BM * SKP;
    constexpr int BSZ = BN * SKP;
    constexpr int BUF = 2 * ASZ + 2 * BSZ;
    extern __shared__ __nv_bfloat16 dsm[];

    const int tid = threadIdx.x;
    const int wid = tid >> 5, lane = tid & 31;
    const int g = lane >> 2, tc = lane & 3;
    const int wm = wid >> 1, wn = wid & 1;
    const int bm = blockIdx.y * BM, bn = blockIdx.x * BN;

    constexpr int AL = (BM * 8) / 256;
    constexpr int BL = (BN * 8) / 256;
    uint4 ra[AL];
    uint2 rbh[BL], rbl[BL];

    float acc[2][NI][4];
    #pragma unroll
    for (int mi = 0; mi < 2; ++mi)
        #pragma unroll
        for (int ni = 0; ni < NI; ++ni)
            #pragma unroll
            for (int j = 0; j < 4; ++j) acc[mi][ni][j] = 0.0f;

    auto load_regs = [&](int kt) {
        const int k0 = kt * BK;
        #pragma unroll
        for (int l = 0; l < AL; ++l) {
            int idx = tid + l * 256;
            int r = idx >> 3, c4 = (idx & 7) * 4;
            ra[l] = (bm + r < M)
                ? *(const uint4*)((const uint32_t*)Av + (size_t)(bm + r) * K + k0 + c4)
                : make_uint4(0u, 0u, 0u, 0u);
        }
        #pragma unroll
        for (int l = 0; l < BL; ++l) {
            int idx = tid + l * 256;
            int r = idx >> 3, c4 = (idx & 7) * 4;
            size_t off = (size_t)(bn + r) * K + k0 + c4;
            rbh[l] = *(const uint2*)(Bh_g + off);
            rbl[l] = *(const uint2*)(Bl_g + off);
        }
    };
    auto store_smem = [&](int buf) {
        __nv_bfloat16* Ah = dsm + buf * BUF;
        __nv_bfloat16* Al = Ah + ASZ;
        __nv_bfloat16* Bh = Al + ASZ;
        __nv_bfloat16* Bl = Bh + BSZ;
        #pragma unroll
        for (int l = 0; l < AL; ++l) {
            int idx = tid + l * 256;
            int r = idx >> 3, c4 = (idx & 7) * 4;
            uint2 hi, lo;
            if (AP) prmt_split(ra[l], hi, lo);
            else    cvt_split(*(float4*)&ra[l], hi, lo);
            *(uint2*)&Ah[r * SKP + c4] = hi;
            *(uint2*)&Al[r * SKP + c4] = lo;
        }
        #pragma unroll
        for (int l = 0; l < BL; ++l) {
            int idx = tid + l * 256;
            int r = idx >> 3, c4 = (idx & 7) * 4;
            *(uint2*)&Bh[r * SKP + c4] = rbh[l];
            *(uint2*)&Bl[r * SKP + c4] = rbl[l];
        }
    };
    auto compute = [&](int buf) {
        const __nv_bfloat16* Ah = dsm + buf * BUF;
        const __nv_bfloat16* Al = Ah + ASZ;
        const __nv_bfloat16* Bh = Al + ASZ;
        const __nv_bfloat16* Bl = Bh + BSZ;
        #pragma unroll
        for (int ks = 0; ks < BK; ks += 16) {
            uint32_t ah[2][4], al[2][4];
            #pragma unroll
            for (int mi = 0; mi < 2; ++mi) {
                int rb_ = wm * 32 + mi * 16 + g;
                const __nv_bfloat16* ph = &Ah[rb_ * SKP + ks + 2 * tc];
                ah[mi][0] = *(const uint32_t*)ph;
                ah[mi][1] = *(const uint32_t*)(ph + 8 * SKP);
                ah[mi][2] = *(const uint32_t*)(ph + 8);
                ah[mi][3] = *(const uint32_t*)(ph + 8 * SKP + 8);
                const __nv_bfloat16* pl = &Al[rb_ * SKP + ks + 2 * tc];
                al[mi][0] = *(const uint32_t*)pl;
                al[mi][1] = *(const uint32_t*)(pl + 8 * SKP);
                al[mi][2] = *(const uint32_t*)(pl + 8);
                al[mi][3] = *(const uint32_t*)(pl + 8 * SKP + 8);
            }
            #pragma unroll
            for (int ni = 0; ni < NI; ++ni) {
                int nb = wn * (BN / 2) + ni * 8 + g;
                const __nv_bfloat16* pbh = &Bh[nb * SKP + ks + 2 * tc];
                uint32_t bh0 = *(const uint32_t*)pbh;
                uint32_t bh1 = *(const uint32_t*)(pbh + 8);
                const __nv_bfloat16* pbl = &Bl[nb * SKP + ks + 2 * tc];
                uint32_t bl0 = *(const uint32_t*)pbl;
                uint32_t bl1 = *(const uint32_t*)(pbl + 8);
                #pragma unroll
                for (int mi = 0; mi < 2; ++mi) {
                    MMA_BF16(acc[mi][ni], ah[mi], bh0, bh1);
                    MMA_BF16(acc[mi][ni], ah[mi], bl0, bl1);
                    MMA_BF16(acc[mi][ni], al[mi], bh0, bh1);
                }
            }
        }
    };

    load_regs(0);
    store_smem(0);
    __syncthreads();
    const int nk = K / BK;
    for (int kt = 0; kt < nk; ++kt) {
        if (kt + 1 < nk) load_regs(kt + 1);
        compute(kt & 1);
        if (kt + 1 < nk) store_smem((kt + 1) & 1);
        __syncthreads();
    }

    #pragma unroll
    for (int ni = 0; ni < NI; ++ni) {
        int n0 = bn + wn * (BN / 2) + ni * 8 + 2 * tc;
        float b0 = 0.f, b1 = 0.f;
        if (EPI >= 1) { b0 = __ldg(&bias[n0]); b1 = __ldg(&bias[n0 + 1]); }
        #pragma unroll
        for (int mi = 0; mi < 2; ++mi) {
            int m0 = bm + wm * 32 + mi * 16 + g;
            float v0 = acc[mi][ni][0] + b0, v1 = acc[mi][ni][1] + b1;
            float v2 = acc[mi][ni][2] + b0, v3 = acc[mi][ni][3] + b1;
            apply_epi(EPI, v0); apply_epi(EPI, v1); apply_epi(EPI, v2); apply_epi(EPI, v3);
            if (OP) {
                if (m0 < M)     *(uint2*)((uint32_t*)Cv + (size_t)m0 * N + n0)       = make_uint2(pk(v0), pk(v1));
                if (m0 + 8 < M) *(uint2*)((uint32_t*)Cv + (size_t)(m0 + 8) * N + n0) = make_uint2(pk(v2), pk(v3));
            } else {
                if (m0 < M)     *(float2*)((float*)Cv + (size_t)m0 * N + n0)       = make_float2(v0, v1);
                if (m0 + 8 < M) *(float2*)((float*)Cv + (size_t)(m0 + 8) * N + n0) = make_float2(v2, v3);
            }
        }
    }
}

// ================== fused 2-layer GEMM (A packed, B pre-split; R11 layout) ==================
template <int K1, int N1, int N2, int EPI2>
__global__ void __launch_bounds__(256)
k_fused(const uint32_t* __restrict__ A,
        const __nv_bfloat16* __restrict__ B1h, const __nv_bfloat16* __restrict__ B1l,
        const float* __restrict__ b1,
        const __nv_bfloat16* __restrict__ B2h, const __nv_bfloat16* __restrict__ B2l,
        const float* __restrict__ b2, float* __restrict__ C, int M) {
    constexpr int BM = 128, BK = 32, SKP = 40;
    constexpr int TSKP = N1 + 8;
    constexpr int NI1 = N1 / 16;
    constexpr int BN2 = (N2 > 128) ? 128 : N2;
    constexpr int NI2 = BN2 / 16;
    constexpr int NH = N2 / BN2;
    constexpr int BNMAX = (N1 > BN2) ? N1 : BN2;
    constexpr int ASZ = BM * SKP;
    constexpr int BSZ = BNMAX * SKP;
    extern __shared__ __nv_bfloat16 dsm[];
    __nv_bfloat16* Ah = dsm;
    __nv_bfloat16* Al = Ah + ASZ;
    __nv_bfloat16* Bh = Al + ASZ;
    __nv_bfloat16* Bl = Bh + BSZ;
    __nv_bfloat16* Th = Bl + BSZ;
    __nv_bfloat16* Tl = Th + BM * TSKP;

    const int tid = threadIdx.x;
    const int wid = tid >> 5, lane = tid & 31;
    const int g = lane >> 2, tc = lane & 3;
    const int wm = wid >> 1, wn = wid & 1;
    const int bm = blockIdx.y * BM;

    // ---------- stage 1 ----------
    {
        float acc[2][NI1][4];
        #pragma unroll
        for (int mi = 0; mi < 2; ++mi)
            #pragma unroll
            for (int ni = 0; ni < NI1; ++ni)
                #pragma unroll
                for (int j = 0; j < 4; ++j) acc[mi][ni][j] = 0.0f;

        for (int kt = 0; kt < K1 / BK; ++kt) {
            const int k0 = kt * BK;
            if (kt > 0) __syncthreads();
            #pragma unroll
            for (int l = 0; l < (BM * 8) / 256; ++l) {
                int idx = tid + l * 256;
                int r = idx >> 3, c4 = (idx & 7) * 4;
                uint4 p = (bm + r < M) ? *(const uint4*)(A + (size_t)(bm + r) * K1 + k0 + c4)
                                       : make_uint4(0u, 0u, 0u, 0u);
                uint2 hi, lo; prmt_split(p, hi, lo);
                *(uint2*)&Ah[r * SKP + c4] = hi;
                *(uint2*)&Al[r * SKP + c4] = lo;
            }
            #pragma unroll
            for (int l = 0; l < (N1 * 8) / 256; ++l) {
                int idx = tid + l * 256;
                int r = idx >> 3, c4 = (idx & 7) * 4;
                size_t off = (size_t)r * K1 + k0 + c4;
                *(uint2*)&Bh[r * SKP + c4] = *(const uint2*)(B1h + off);
                *(uint2*)&Bl[r * SKP + c4] = *(const uint2*)(B1l + off);
            }
            __syncthreads();
            #pragma unroll
            for (int ks = 0; ks < BK; ks += 16) {
                uint32_t ah[2][4], al[2][4];
                #pragma unroll
                for (int mi = 0; mi < 2; ++mi) {
                    int rb_ = wm * 32 + mi * 16 + g;
                    const __nv_bfloat16* ph = &Ah[rb_ * SKP + ks + 2 * tc];
                    ah[mi][0] = *(const uint32_t*)ph;
                    ah[mi][1] = *(const uint32_t*)(ph + 8 * SKP);
                    ah[mi][2] = *(const uint32_t*)(ph + 8);
                    ah[mi][3] = *(const uint32_t*)(ph + 8 * SKP + 8);
                    const __nv_bfloat16* pl = &Al[rb_ * SKP + ks + 2 * tc];
                    al[mi][0] = *(const uint32_t*)pl;
                    al[mi][1] = *(const uint32_t*)(pl + 8 * SKP);
                    al[mi][2] = *(const uint32_t*)(pl + 8);
                    al[mi][3] = *(const uint32_t*)(pl + 8 * SKP + 8);
                }
                #pragma unroll
                for (int ni = 0; ni < NI1; ++ni) {
                    int nb = wn * (N1 / 2) + ni * 8 + g;
                    const __nv_bfloat16* pbh = &Bh[nb * SKP + ks + 2 * tc];
                    uint32_t bh0 = *(const uint32_t*)pbh;
                    uint32_t bh1 = *(const uint32_t*)(pbh + 8);
                    const __nv_bfloat16* pbl = &Bl[nb * SKP + ks + 2 * tc];
                    uint32_t bl0 = *(const uint32_t*)pbl;
                    uint32_t bl1 = *(const uint32_t*)(pbl + 8);
                    #pragma unroll
                    for (int mi = 0; mi < 2; ++mi) {
                        MMA_BF16(acc[mi][ni], ah[mi], bh0, bh1);
                        MMA_BF16(acc[mi][ni], ah[mi], bl0, bl1);
                        MMA_BF16(acc[mi][ni], al[mi], bh0, bh1);
                    }
                }
            }
        }
        __syncthreads();
        #pragma unroll
        for (int ni = 0; ni < NI1; ++ni) {
            int n0 = wn * (N1 / 2) + ni * 8 + 2 * tc;
            float b0 = __ldg(&b1[n0]), b1v = __ldg(&b1[n0 + 1]);
            #pragma unroll
            for (int mi = 0; mi < 2; ++mi) {
                int r0 = wm * 32 + mi * 16 + g;
                float v0 = fmaxf(acc[mi][ni][0] + b0, 0.f);
                float v1 = fmaxf(acc[mi][ni][1] + b1v, 0.f);
                float v2 = fmaxf(acc[mi][ni][2] + b0, 0.f);
                float v3 = fmaxf(acc[mi][ni][3] + b1v, 0.f);
                uint32_t hi, lo;
                split2(v0, v1, hi, lo);
                *(uint32_t*)&Th[r0 * TSKP + n0] = hi;
                *(uint32_t*)&Tl[r0 * TSKP + n0] = lo;
                split2(v2, v3, hi, lo);
                *(uint32_t*)&Th[(r0 + 8) * TSKP + n0] = hi;
                *(uint32_t*)&Tl[(r0 + 8) * TSKP + n0] = lo;
            }
        }
        __syncthreads();
    }

    // ---------- stage 2 ----------
    for (int h = 0; h < NH; ++h) {
        const int nbase = h * BN2;
        float acc[2][NI2][4];
        #pragma unroll
        for (int mi = 0; mi < 2; ++mi)
            #pragma unroll
            for (int ni = 0; ni < NI2; ++ni)
                #pragma unroll
                for (int j = 0; j < 4; ++j) acc[mi][ni][j] = 0.0f;

        for (int kt = 0; kt < N1 / BK; ++kt) {
            const int k0 = kt * BK;
            if (h > 0 || kt > 0) __syncthreads();
            #pragma unroll
            for (int l = 0; l < (BN2 * 8) / 256; ++l) {
                int idx = tid + l * 256;
                int r = idx >> 3, c4 = (idx & 7) * 4;
                size_t off = (size_t)(nbase + r) * N1 + k0 + c4;
                *(uint2*)&Bh[r * SKP + c4] = *(const uint2*)(B2h + off);
                *(uint2*)&Bl[r * SKP + c4] = *(const uint2*)(B2l + off);
            }
            __syncthreads();
            #pragma unroll
            for (int ks = 0; ks < BK; ks += 16) {
                const int kk = k0 + ks;
                uint32_t ah[2][4], al[2][4];
                #pragma unroll
                for (int mi = 0; mi < 2; ++mi) {
                    int rb_ = wm * 32 + mi * 16 + g;
                    const __nv_bfloat16* ph = &Th[rb_ * TSKP + kk + 2 * tc];
                    ah[mi][0] = *(const uint32_t*)ph;
                    ah[mi][1] = *(const uint32_t*)(ph + 8 * TSKP);
                    ah[mi][2] = *(const uint32_t*)(ph + 8);
                    ah[mi][3] = *(const uint32_t*)(ph + 8 * TSKP + 8);
                    const __nv_bfloat16* pl = &Tl[rb_ * TSKP + kk + 2 * tc];
                    al[mi][0] = *(const uint32_t*)pl;
                    al[mi][1] = *(const uint32_t*)(pl + 8 * TSKP);
                    al[mi][2] = *(const uint32_t*)(pl + 8);
                    al[mi][3] = *(const uint32_t*)(pl + 8 * TSKP + 8);
                }
                #pragma unroll
                for (int ni = 0; ni < NI2; ++ni) {
                    int nb = wn * (BN2 / 2) + ni * 8 + g;
                    const __nv_bfloat16* pbh = &Bh[nb * SKP + ks + 2 * tc];
                    uint32_t bh0 = *(const uint32_t*)pbh;
                    uint32_t bh1 = *(const uint32_t*)(pbh + 8);
                    const __nv_bfloat16* pbl = &Bl[nb * SKP + ks + 2 * tc];
                    uint32_t bl0 = *(const uint32_t*)pbl;
                    uint32_t bl1 = *(const uint32_t*)(pbl + 8);
                    #pragma unroll
                    for (int mi = 0; mi < 2; ++mi) {
                        MMA_BF16(acc[mi][ni], ah[mi], bh0, bh1);
                        MMA_BF16(acc[mi][ni], ah[mi], bl0, bl1);
                        MMA_BF16(acc[mi][ni], al[mi], bh0, bh1);
                    }
                }
            }
        }
        #pragma unroll
        for (int ni = 0; ni < NI2; ++ni) {
            int nl = wn * (BN2 / 2) + ni * 8 + 2 * tc;
            int n0 = nbase + nl;
            float b0 = 0.f, b1v = 0.f;
            if (EPI2 >= 1) { b0 = __ldg(&b2[n0]); b1v = __ldg(&b2[n0 + 1]); }
            #pragma unroll
            for (int mi = 0; mi < 2; ++mi) {
                int m0 = bm + wm * 32 + mi * 16 + g;
                float v0 = acc[mi][ni][0] + b0, v1 = acc[mi][ni][1] + b1v;
                float v2 = acc[mi][ni][2] + b0, v3 = acc[mi][ni][3] + b1v;
                apply_epi(EPI2, v0); apply_epi(EPI2, v1);
                apply_epi(EPI2, v2); apply_epi(EPI2, v3);
                if (m0 < M)     *(float2*)&C[(size_t)m0 * N2 + n0]       = make_float2(v0, v1);
                if (m0 + 8 < M) *(float2*)&C[(size_t)(m0 + 8) * N2 + n0] = make_float2(v2, v3);
            }
        }
    }
}

// -------- SpMM aggregation: warp per node, float4 lanes, 2 edges/iter, packed out --------
__global__ void __launch_bounds__(256)
k_spmm(const float* __restrict__ hw, const float* __restrict__ bias,
       uint32_t* __restrict__ out) {
    int warp = (blockIdx.x * blockDim.x + threadIdx.x) >> 5;
    int lane = threadIdx.x & 31;
    if (warp >= NN) return;
    int node = warp;
    int half = lane >> 4, hl = lane & 15;
    float dinv_i = g_dinv[node];
    float selfc = dinv_i * dinv_i;

    float4 acc = make_float4(0.f, 0.f, 0.f, 0.f);
    if (half == 0) {
        float4 hv = *(const float4*)&hw[(size_t)node * D_H2 + hl * 4];
        acc.x = selfc * hv.x; acc.y = selfc * hv.y;
        acc.z = selfc * hv.z; acc.w = selfc * hv.w;
    }

    int start = g_rowptr[node], end = g_rowptr[node + 1];
    for (int base = start; base < end; base += 32) {
        int p = base + lane;
        int s = 0; float c = 0.0f;
        if (p < end) {
            int2 e = g_csr[p];
            s = e.x;
            c = __int_as_float(e.y);
        }
        #pragma unroll
        for (int j = 0; j < 16; ++j) {
            int sl = 2 * j + half;                        // half 0: even edges, half 1: odd
            float cj = __shfl_sync(0xffffffffu, c, sl);
            int   sj = __shfl_sync(0xffffffffu, s, sl);
            if (cj != 0.0f) {                             // half-warp-uniform tail skip
                float4 hv = *(const float4*)&hw[(size_t)sj * D_H2 + hl * 4];
                acc.x += cj * hv.x; acc.y += cj * hv.y;
                acc.z += cj * hv.z; acc.w += cj * hv.w;
            }
        }
    }
    // combine the two half-warp accumulators
    acc.x += __shfl_xor_sync(0xffffffffu, acc.x, 16);
    acc.y += __shfl_xor_sync(0xffffffffu, acc.y, 16);
    acc.z += __shfl_xor_sync(0xffffffffu, acc.z, 16);
    acc.w += __shfl_xor_sync(0xffffffffu, acc.w, 16);

    if (half == 0) {
        float4 b = *(const float4*)&bias[hl * 4];
        uint4 o;
        o.x = pk(fmaxf(acc.x + b.x, 0.0f));
        o.y = pk(fmaxf(acc.y + b.y, 0.0f));
        o.z = pk(fmaxf(acc.z + b.z, 0.0f));
        o.w = pk(fmaxf(acc.w + b.w, 0.0f));
        *(uint4*)&out[(size_t)node * D_H2 + hl * 4] = o;
    }
}

// ---------------- launch ----------------
extern "C" void kernel_launch(void* const* d_in, const int* in_sizes, int n_in,
                              void* d_out, int out_size) {
    const float* x  = (const float*)d_in[0];
    const int*   ei = (const int*)d_in[1];      // int32 (JAX x64 disabled)
    const float* ew = (const float*)d_in[2];
    const float* enc1_w = (const float*)d_in[3];
    const float* enc1_b = (const float*)d_in[4];
    const float* enc2_w = (const float*)d_in[5];
    const float* enc2_b = (const float*)d_in[6];
    const float* gcn1_w = (const float*)d_in[7];
    const float* gcn1_b = (const float*)d_in[8];
    const float* gcn2_w = (const float*)d_in[9];
    const float* gcn2_b = (const float*)d_in[10];
    const float* dec1_w = (const float*)d_in[11];
    const float* dec1_b = (const float*)d_in[12];
    const float* dec2_w = (const float*)d_in[13];
    const float* dec2_b = (const float*)d_in[14];
    float* out = (float*)d_out;

    const int* srcp = ei;
    const int* dstp = ei + EE;

    uint32_t *h1, *h2, *g;
    float *hw;
    cudaGetSymbolAddress((void**)&h1, g_h1);
    cudaGetSymbolAddress((void**)&h2, g_h2);
    cudaGetSymbolAddress((void**)&hw, g_hw);
    cudaGetSymbolAddress((void**)&g,  g_g);
    __nv_bfloat16 *wh, *wl;
    cudaGetSymbolAddress((void**)&wh, g_wh);
    cudaGetSymbolAddress((void**)&wl, g_wl);

    // dynamic smem sizes (bytes) — R11 tile layout
    const int SM128  = 2 * (2 * 128 * 40 + 2 * 128 * 40) * 2;               // 81920
    const int SM64   = 2 * (2 * 128 * 40 + 2 * 64 * 40) * 2;                // 61440
    const int SMF_E  = (2 * 128 * 40 + 2 * 64 * 40 + 2 * 128 * 72) * 2;     // 67584
    const int SMF_D  = (2 * 128 * 40 + 2 * 128 * 40 + 2 * 128 * 136) * 2;   // 110592
    cudaFuncSetAttribute(k_mma<128, 1, 0, 1>, cudaFuncAttributeMaxDynamicSharedMemorySize, SM128);
    cudaFuncSetAttribute(k_mma<64, 0, 1, 0>,  cudaFuncAttributeMaxDynamicSharedMemorySize, SM64);
    cudaFuncSetAttribute(k_fused<128, 64, 64, 0>,  cudaFuncAttributeMaxDynamicSharedMemorySize, SMF_E);
    cudaFuncSetAttribute(k_fused<64, 128, 256, 2>, cudaFuncAttributeMaxDynamicSharedMemorySize, SMF_D);

    const int TB = 256;
    int gridN = (NN + TB - 1) / TB;
    int gridE = (EE + TB - 1) / TB;
    const int NB = (NN + 1023) / 1024;

    // ---- fork: CSR build on a side stream ----
    cudaStream_t side;
    cudaStreamCreateWithFlags(&side, cudaStreamNonBlocking);
    cudaEvent_t e0, e1;
    cudaEventCreateWithFlags(&e0, cudaEventDisableTiming);
    cudaEventCreateWithFlags(&e1, cudaEventDisableTiming);

    cudaEventRecord(e0, 0);
    cudaStreamWaitEvent(side, e0, 0);
    k_init_counts<<<gridN, TB, 0, side>>>();
    k_count<<<gridE, TB, 0, side>>>(dstp, ew);
    k_dinv<<<gridN, TB, 0, side>>>();
    k_scan1<<<NB, 1024, 0, side>>>(NN);
    k_scan2<<<1, 64, 0, side>>>(NB, NN);
    k_scan3<<<NB, 1024, 0, side>>>(NN);
    k_fill<<<gridE, TB, 0, side>>>(srcp, dstp, ew);
    cudaEventRecord(e1, side);

    const int MY = (NN + 127) / 128;   // 391

    // main stream: split weights, enc1 (champion config), fused enc2+gcn1-matmul
    k_splitw<<<(W_TOTAL + 255) / 256, 256>>>(enc1_w, enc2_w, gcn1_w, gcn2_w, dec1_w, dec2_w);
    k_mma<128, 1, 0, 1><<<dim3(1, MY), 256, SM128>>>(x, wh + OFF_ENC1, wl + OFF_ENC1,
                                                     enc1_b, h1, NN, D_H1, D_IN);
    k_fused<128, 64, 64, 0><<<dim3(1, MY), 256, SMF_E>>>(h1, wh + OFF_ENC2, wl + OFF_ENC2,
                                                         enc2_b, wh + OFF_GCN1, wl + OFF_GCN1,
                                                         nullptr, hw, NN);

    // ---- join: aggregation needs the CSR ----
    cudaStreamWaitEvent(0, e1, 0);
    k_spmm<<<(NN * 32 + TB - 1) / TB, TB>>>(hw, gcn1_b, g);
    k_mma<64, 0, 1, 0><<<dim3(1, MY), 256, SM64>>>(g, wh + OFF_GCN2, wl + OFF_GCN2,
                                                   nullptr, hw, NN, D_H2, D_H2);
    k_spmm<<<(NN * 32 + TB - 1) / TB, TB>>>(hw, gcn2_b, h2);

    // fused dec1+dec2 (bias+relu, then bias+sigmoid)
    k_fused<64, 128, 256, 2><<<dim3(1, MY), 256, SMF_D>>>(h2, wh + OFF_DEC1, wl + OFF_DEC1,
                                                          dec1_b, wh + OFF_DEC2, wl + OFF_DEC2,
                                                          dec2_b, out, NN);
    // note: side stream + events intentionally not destroyed (capture-safe; few calls)
}